// round 9
// baseline (speedup 1.0000x reference)
#include <cuda_runtime.h>
#include <cstdint>

#define HW   (128*128)        // 16384 pixels per (b,c) plane
#define CHW  (64*HW)          // one batch image, 64 channels
#define NPIX (4*HW)           // total pixels across batch

// Scratch tensors (allocation-free rule: __device__ globals)
__device__ float g_Q[4*CHW];
__device__ float g_V[4*CHW];
__device__ float g_O[4*CHW];

// packed fp32x2 FMA (SASS FFMA2) — only reachable via explicit PTX
__device__ __forceinline__ uint64_t fma2(uint64_t a, uint64_t b, uint64_t c) {
    uint64_t d;
    asm("fma.rn.f32x2 %0, %1, %2, %3;" : "=l"(d) : "l"(a), "l"(b), "l"(c));
    return d;
}
__device__ __forceinline__ void unpack2(float& lo, float& hi, uint64_t v) {
    asm("mov.b64 {%0, %1}, %2;" : "=f"(lo), "=f"(hi) : "l"(v));
}

// ---------------------------------------------------------------------------
// conv1x1 body: out[b,f,p] = sum_c w[f,c]*in[b,c,p] + bias[f] (+ resid)
// Tile 64f x 256px, 256 threads, 8f x 8px per thread, ALL math as FFMA2.
// smem: xs[64][256] activations (64KB) + ws2[64][128] lane-DUPLICATED weights
// (32KB: each w value stored twice so weight pairs load directly as b64).
// Per k-step per thread: 4 broadcast LDS.128 (w) + 2 strided LDS.128 (x),
// 32 FFMA2 (= 64 FMA).
// ---------------------------------------------------------------------------
__device__ __forceinline__ void conv1x1_body(
    const float* __restrict__ in, const float* __restrict__ w,
    const float* __restrict__ bias, const float* __restrict__ resid,
    float* __restrict__ out)
{
    extern __shared__ float sm[];
    float* xs  = sm;             // [64][256] activation tile (64KB)
    float* ws2 = sm + 64*256;    // [64][128] duplicated weights: ws2[c*128+f*2{,+1}]
    float* bs  = ws2 + 64*128;   // [64]

    int tid = threadIdx.x;

    // duplicate-store weights (i = f*64 + c)
    for (int i = tid; i < 4096; i += 256) {
        int f = i >> 6, c = i & 63;
        float v = w[i];
        ws2[c*128 + f*2]     = v;
        ws2[c*128 + f*2 + 1] = v;
    }
    if (tid < 64) bs[tid] = bias[tid];

    int pix0 = blockIdx.x * 256;
    int b    = pix0 >> 14;
    int p    = pix0 & (HW - 1);
    const float* inp = in + (size_t)b*CHW + p;

    const float4* inp4 = (const float4*)inp;
    float4* xs4 = (float4*)xs;
    #pragma unroll
    for (int i = tid; i < 4096; i += 256) {
        int c = i >> 6, q = i & 63;
        xs4[i] = inp4[c*(HW/4) + q];
    }
    __syncthreads();

    int fg   = tid >> 5;     // features fg*8 .. fg*8+7 (uniform per warp)
    int lane = tid & 31;     // pixels lane*4..+3 and +128..+131

    uint64_t acc[8][4];      // [feature][pixel-pair], packed fp32x2
    #pragma unroll
    for (int j = 0; j < 8; j++)
        #pragma unroll
        for (int k = 0; k < 4; k++) acc[j][k] = 0ull;   // {+0.f, +0.f}

    const float* wp = ws2 + fg*16;
    const float* xp = xs  + lane*4;

    // software pipeline: activation pair-loads one k-step ahead
    ulonglong2 x0 = *(const ulonglong2*)(xp);
    ulonglong2 x1 = *(const ulonglong2*)(xp + 128);

    #pragma unroll 4
    for (int c = 0; c < 64; c++) {
        ulonglong2 x0n, x1n;
        if (c < 63) {
            x0n = *(const ulonglong2*)(xp + (c+1)*256);
            x1n = *(const ulonglong2*)(xp + (c+1)*256 + 128);
        }
        // weight pairs (both lanes equal), broadcast LDS.128 x4
        ulonglong2 wA = *(const ulonglong2*)(wp + c*128);
        ulonglong2 wB = *(const ulonglong2*)(wp + c*128 + 4);
        ulonglong2 wC = *(const ulonglong2*)(wp + c*128 + 8);
        ulonglong2 wD = *(const ulonglong2*)(wp + c*128 + 12);

        uint64_t wr[8] = {wA.x, wA.y, wB.x, wB.y, wC.x, wC.y, wD.x, wD.y};
        uint64_t xr[4] = {x0.x, x0.y, x1.x, x1.y};
        #pragma unroll
        for (int j = 0; j < 8; j++)
            #pragma unroll
            for (int k = 0; k < 4; k++)
                acc[j][k] = fma2(wr[j], xr[k], acc[j][k]);

        x0 = x0n; x1 = x1n;
    }

    float* outp = out + (size_t)b*CHW + p + lane*4;
    const float* rp = resid ? (resid + (size_t)b*CHW + p + lane*4) : nullptr;
    #pragma unroll
    for (int j = 0; j < 8; j++) {
        int f = fg*8 + j;
        float bv = bs[f];
        #pragma unroll
        for (int h = 0; h < 2; h++) {
            float4 r;
            unpack2(r.x, r.y, acc[j][h*2]);
            unpack2(r.z, r.w, acc[j][h*2 + 1]);
            r.x += bv; r.y += bv; r.z += bv; r.w += bv;
            if (rp) {
                float4 rv = *(const float4*)(rp + (size_t)f*HW + h*128);
                r.x += rv.x; r.y += rv.y; r.z += rv.z; r.w += rv.w;
            }
            *(float4*)(outp + (size_t)f*HW + h*128) = r;
        }
    }
}

__global__ void __launch_bounds__(256, 2) qv_conv_kernel(
    const float* __restrict__ x,  const float* __restrict__ y,
    const float* __restrict__ wx, const float* __restrict__ bx,
    const float* __restrict__ wy, const float* __restrict__ by,
    float* __restrict__ Q, float* __restrict__ V)
{
    if (blockIdx.y == 0) conv1x1_body(y, wy, by, nullptr, Q);
    else                 conv1x1_body(x, wx, bx, nullptr, V);
}

__global__ void __launch_bounds__(256, 2) out_conv_kernel(
    const float* __restrict__ in, const float* __restrict__ w,
    const float* __restrict__ bias, const float* __restrict__ resid,
    float* __restrict__ out)
{
    conv1x1_body(in, w, bias, resid, out);
}

// ---------------------------------------------------------------------------
// Local attention (5x5 window, zero-padded) — R7 high-occupancy version
// (measured-good). 512 threads, 1 px/thread, two 32-channel chunks, 92KB smem.
// ---------------------------------------------------------------------------
#define HT 16
#define WT 32
#define HR (HT + 4)     // 20
#define WC (WT + 4)     // 36
#define NPOS (HR * WC)  // 720
#define CCH 32          // channels per chunk
#define ATTN_SMEM (CCH*NPOS*4)   // 92160 B

__device__ __forceinline__ void load_halo_chunk(
    const float* __restrict__ src,
    float* __restrict__ s, int tid, int h0, int w0)
{
    #pragma unroll 5
    for (int i = tid; i < CCH*NPOS; i += 512) {
        int c   = i / NPOS;
        int pos = i - c*NPOS;
        int r   = pos / WC;
        int col = pos - r*WC;
        int gh  = h0 + r - 2;
        int gw  = w0 + col - 2;
        float v = 0.f;
        if ((unsigned)gh < 128u && (unsigned)gw < 128u)
            v = src[c*HW + gh*128 + gw];
        s[i] = v;
    }
}

__global__ void __launch_bounds__(512, 1) attn_kernel(
    const float* __restrict__ Q, const float* __restrict__ V,
    float* __restrict__ O)
{
    extern __shared__ float s[];   // [CCH][NPOS]

    int tid = threadIdx.x;
    int wx  = tid & 31;
    int hy  = tid >> 5;
    int b   = blockIdx.z;
    int h0  = blockIdx.y * HT;
    int w0  = blockIdx.x * WT;

    float A[25];
    #pragma unroll
    for (int k = 0; k < 25; k++) A[k] = 0.f;

    // ---- scores: two 32-channel chunks ----
    const float* Qb = Q + (size_t)b*CHW;
    #pragma unroll
    for (int ck = 0; ck < 2; ck++) {
        load_halo_chunk(Qb + ck*CCH*HW, s, tid, h0, w0);
        __syncthreads();

        const float* base0 = s + hy*WC + wx;
        for (int c = 0; c < CCH; c++) {
            const float* qs = base0 + c*NPOS;
            float n[25];
            #pragma unroll
            for (int j = 0; j < 5; j++)
                #pragma unroll
                for (int i = 0; i < 5; i++)
                    n[j*5+i] = qs[j*WC + i];
            float q = n[12];
            #pragma unroll
            for (int k = 0; k < 25; k++)
                A[k] += q * n[k];
        }
        __syncthreads();
    }

    // ---- softmax over 25 neighbors ----
    {
        float m = A[0];
        #pragma unroll
        for (int k = 1; k < 25; k++) m = fmaxf(m, A[k]);
        float sum = 0.f;
        #pragma unroll
        for (int k = 0; k < 25; k++) { A[k] = __expf(A[k] - m); sum += A[k]; }
        float inv = 1.f/sum;
        #pragma unroll
        for (int k = 0; k < 25; k++) A[k] *= inv;
    }

    // ---- aggregate: two 32-channel chunks ----
    const float* Vb = V + (size_t)b*CHW;
    float* Ob = O + (size_t)b*CHW + (h0 + hy)*128 + (w0 + wx);
    #pragma unroll
    for (int ck = 0; ck < 2; ck++) {
        load_halo_chunk(Vb + ck*CCH*HW, s, tid, h0, w0);
        __syncthreads();

        const float* base0 = s + hy*WC + wx;
        for (int c = 0; c < CCH; c++) {
            const float* vs = base0 + c*NPOS;
            float o = 0.f;
            #pragma unroll
            for (int j = 0; j < 5; j++)
                #pragma unroll
                for (int i = 0; i < 5; i++)
                    o += A[j*5+i] * vs[j*WC + i];
            Ob[(size_t)(ck*CCH + c)*HW] = o;
        }
        __syncthreads();
    }
}

// ---------------------------------------------------------------------------
extern "C" void kernel_launch(void* const* d_in, const int* in_sizes, int n_in,
                              void* d_out, int out_size)
{
    const float* x  = (const float*)d_in[0];
    const float* y  = (const float*)d_in[1];
    const float* wx = (const float*)d_in[2];
    const float* bx = (const float*)d_in[3];
    const float* wy = (const float*)d_in[4];
    const float* by = (const float*)d_in[5];
    const float* wo = (const float*)d_in[6];
    const float* bo = (const float*)d_in[7];
    float* out = (float*)d_out;

    void *pQ, *pV, *pO;
    cudaGetSymbolAddress(&pQ, g_Q);
    cudaGetSymbolAddress(&pV, g_V);
    cudaGetSymbolAddress(&pO, g_O);

    const int conv_smem = (64*256 + 64*128 + 64) * 4;   // 98560 B
    cudaFuncSetAttribute(qv_conv_kernel,  cudaFuncAttributeMaxDynamicSharedMemorySize, conv_smem);
    cudaFuncSetAttribute(out_conv_kernel, cudaFuncAttributeMaxDynamicSharedMemorySize, conv_smem);
    cudaFuncSetAttribute(attn_kernel,     cudaFuncAttributeMaxDynamicSharedMemorySize, ATTN_SMEM);

    // q = wy @ y + by ; v = wx @ x + bx  (one fused launch, gridDim.y selects)
    qv_conv_kernel<<<dim3(NPIX/256, 2), 256, conv_smem>>>(
        x, y, wx, bx, wy, by, (float*)pQ, (float*)pV);

    // scores + softmax + aggregate
    attn_kernel<<<dim3(128/WT, 128/HT, 4), 512, ATTN_SMEM>>>(
        (const float*)pQ, (const float*)pV, (float*)pO);

    // out = wo @ O + bo + x
    out_conv_kernel<<<NPIX/256, 256, conv_smem>>>((const float*)pO, wo, bo, x, out);
}

// round 10
// speedup vs baseline: 1.0189x; 1.0189x over previous
#include <cuda_runtime.h>
#include <cstdint>

#define HW   (128*128)        // 16384 pixels per (b,c) plane
#define CHW  (64*HW)          // one batch image, 64 channels
#define NPIX (4*HW)           // total pixels across batch

// Scratch tensors (allocation-free rule: __device__ globals)
__device__ float g_Q[4*CHW];
__device__ float g_V[4*CHW];
__device__ float g_O[4*CHW];

// ---------------------------------------------------------------------------
// TF32 tensor-core helpers (legacy mma.sync — PTX sm_80+, no arch suffix)
// ---------------------------------------------------------------------------
__device__ __forceinline__ uint32_t cvt_tf32(float x) {
    uint32_t r;
    asm("cvt.rna.tf32.f32 %0, %1;" : "=r"(r) : "f"(x));
    return r;
}

__device__ __forceinline__ void mma_tf32(float* d, const uint32_t* a,
                                         const uint32_t* b) {
    asm volatile(
        "mma.sync.aligned.m16n8k8.row.col.f32.tf32.tf32.f32 "
        "{%0,%1,%2,%3}, {%4,%5,%6,%7}, {%8,%9}, {%0,%1,%2,%3};\n"
        : "+f"(d[0]), "+f"(d[1]), "+f"(d[2]), "+f"(d[3])
        : "r"(a[0]), "r"(a[1]), "r"(a[2]), "r"(a[3]), "r"(b[0]), "r"(b[1]));
}

// ---------------------------------------------------------------------------
// conv1x1 via TF32 mma.sync, 3-pass fp32-split (ah*bh + al*bh + ah*bl).
// Per CTA: D[128px, 64f] = A[128px, 64c] * B[64f, 64c]^T, 256 threads, 8 warps.
// Warp w owns px rows 16w..16w+15; loops k-blocks(8) x n-blocks(8).
// smem: As[128][68] fp32 (A-frag loads conflict-free), Bs[64][68], bias.
// Epilogue: D staged through smem [f][132] -> coalesced float4 STG
// with fused bias (+ residual).
// ---------------------------------------------------------------------------
#define AS_STR 68
#define DS_STR 132
#define CONV_SMEM ((128*AS_STR + 64*AS_STR + 64) * 4)   // 52480 B

__device__ __forceinline__ void conv_mma_body(
    const float* __restrict__ in, const float* __restrict__ w,
    const float* __restrict__ bias, const float* __restrict__ resid,
    float* __restrict__ out)
{
    extern __shared__ float sm[];
    float* As = sm;                    // [128][68] activations (px-major)
    float* Bs = sm + 128*AS_STR;       // [64][68]  weights [f][c]
    float* bs = Bs + 64*AS_STR;        // [64]

    int tid = threadIdx.x;

    // ---- load B [f][c] (coalesced; conflict-free STS) ----
    for (int i = tid; i < 4096; i += 256)
        Bs[(i >> 6)*AS_STR + (i & 63)] = w[i];
    if (tid < 64) bs[tid] = bias[tid];

    int pix0 = blockIdx.x * 128;       // 16384 % 128 == 0
    int b    = pix0 >> 14;
    int p    = pix0 & (HW - 1);
    const float* inp = in + (size_t)b*CHW + p;

    // ---- load A transposed to [px][c] (coalesced LDG over px) ----
    for (int i = tid; i < 8192; i += 256) {
        int c = i >> 7, px = i & 127;
        As[px*AS_STR + c] = inp[c*HW + px];
    }
    __syncthreads();

    int wp   = tid >> 5;       // warp id: px rows 16*wp .. 16*wp+15
    int lane = tid & 31;
    int g    = lane >> 2;      // group 0..7
    int t    = lane & 3;       // thread-in-group 0..3

    float acc[8][4];
    #pragma unroll
    for (int nb = 0; nb < 8; nb++)
        #pragma unroll
        for (int j = 0; j < 4; j++) acc[nb][j] = 0.f;

    const float* ap = As + (16*wp + g)*AS_STR + t;
    const float* bp = Bs + g*AS_STR + t;

    #pragma unroll 2
    for (int kb = 0; kb < 8; kb++) {
        // A fragment (m16 k8): rows g, g+8; cols t, t+4 within k-block
        float a[4];
        a[0] = ap[kb*8];
        a[1] = ap[8*AS_STR + kb*8];
        a[2] = ap[kb*8 + 4];
        a[3] = ap[8*AS_STR + kb*8 + 4];
        uint32_t ah[4], al[4];
        #pragma unroll
        for (int j = 0; j < 4; j++) {
            ah[j] = cvt_tf32(a[j]);
            al[j] = __float_as_uint(a[j] - __uint_as_float(ah[j]));
        }

        #pragma unroll
        for (int nb = 0; nb < 8; nb++) {
            // B fragment (k8 n8 col-major): n = nb*8+g, k = t and t+4
            float bv0 = bp[nb*8*AS_STR + kb*8];
            float bv1 = bp[nb*8*AS_STR + kb*8 + 4];
            uint32_t bh[2], bl[2];
            bh[0] = cvt_tf32(bv0);
            bl[0] = __float_as_uint(bv0 - __uint_as_float(bh[0]));
            bh[1] = cvt_tf32(bv1);
            bl[1] = __float_as_uint(bv1 - __uint_as_float(bh[1]));

            mma_tf32(acc[nb], ah, bh);   // hi*hi
            mma_tf32(acc[nb], al, bh);   // lo*hi
            mma_tf32(acc[nb], ah, bl);   // hi*lo
        }
    }
    __syncthreads();

    // ---- stage D to smem as [f][px] (stride 132), conflict-free ----
    float* Ds = sm;                    // [64][132] = 8448 floats (fits in As)
    #pragma unroll
    for (int nb = 0; nb < 8; nb++) {
        int f0 = nb*8 + 2*t;           // cols 2t, 2t+1 of this n-block
        int r0 = 16*wp + g;            // rows g, g+8
        Ds[f0*DS_STR + r0]           = acc[nb][0];
        Ds[(f0+1)*DS_STR + r0]       = acc[nb][1];
        Ds[f0*DS_STR + r0 + 8]       = acc[nb][2];
        Ds[(f0+1)*DS_STR + r0 + 8]   = acc[nb][3];
    }
    __syncthreads();

    // ---- coalesced output: warp wp covers f = wp*8 + r, lanes cover px ----
    float* outp = out + (size_t)b*CHW + p;
    const float* rp = resid ? (resid + (size_t)b*CHW + p) : nullptr;
    #pragma unroll
    for (int r = 0; r < 8; r++) {
        int f = wp*8 + r;
        float4 v = *(const float4*)(Ds + f*DS_STR + lane*4);
        float bv = bs[f];
        v.x += bv; v.y += bv; v.z += bv; v.w += bv;
        if (rp) {
            float4 rv = *(const float4*)(rp + (size_t)f*HW + lane*4);
            v.x += rv.x; v.y += rv.y; v.z += rv.z; v.w += rv.w;
        }
        *(float4*)(outp + (size_t)f*HW + lane*4) = v;
    }
}

__global__ void __launch_bounds__(256, 2) qv_conv_kernel(
    const float* __restrict__ x,  const float* __restrict__ y,
    const float* __restrict__ wx, const float* __restrict__ bx,
    const float* __restrict__ wy, const float* __restrict__ by,
    float* __restrict__ Q, float* __restrict__ V)
{
    if (blockIdx.y == 0) conv_mma_body(y, wy, by, nullptr, Q);
    else                 conv_mma_body(x, wx, bx, nullptr, V);
}

__global__ void __launch_bounds__(256, 2) out_conv_kernel(
    const float* __restrict__ in, const float* __restrict__ w,
    const float* __restrict__ bias, const float* __restrict__ resid,
    float* __restrict__ out)
{
    conv_mma_body(in, w, bias, resid, out);
}

// ---------------------------------------------------------------------------
// Local attention (5x5 window, zero-padded) — R7/R8 high-occupancy version
// (measured-good). 512 threads, 1 px/thread, two 32-channel chunks, 92KB smem.
// ---------------------------------------------------------------------------
#define HT 16
#define WT 32
#define HR (HT + 4)     // 20
#define WC (WT + 4)     // 36
#define NPOS (HR * WC)  // 720
#define CCH 32          // channels per chunk
#define ATTN_SMEM (CCH*NPOS*4)   // 92160 B

__device__ __forceinline__ void load_halo_chunk(
    const float* __restrict__ src,
    float* __restrict__ s, int tid, int h0, int w0)
{
    #pragma unroll 5
    for (int i = tid; i < CCH*NPOS; i += 512) {
        int c   = i / NPOS;
        int pos = i - c*NPOS;
        int r   = pos / WC;
        int col = pos - r*WC;
        int gh  = h0 + r - 2;
        int gw  = w0 + col - 2;
        float v = 0.f;
        if ((unsigned)gh < 128u && (unsigned)gw < 128u)
            v = src[c*HW + gh*128 + gw];
        s[i] = v;
    }
}

__global__ void __launch_bounds__(512, 1) attn_kernel(
    const float* __restrict__ Q, const float* __restrict__ V,
    float* __restrict__ O)
{
    extern __shared__ float s[];   // [CCH][NPOS]

    int tid = threadIdx.x;
    int wx  = tid & 31;
    int hy  = tid >> 5;
    int b   = blockIdx.z;
    int h0  = blockIdx.y * HT;
    int w0  = blockIdx.x * WT;

    float A[25];
    #pragma unroll
    for (int k = 0; k < 25; k++) A[k] = 0.f;

    // ---- scores: two 32-channel chunks ----
    const float* Qb = Q + (size_t)b*CHW;
    #pragma unroll
    for (int ck = 0; ck < 2; ck++) {
        load_halo_chunk(Qb + ck*CCH*HW, s, tid, h0, w0);
        __syncthreads();

        const float* base0 = s + hy*WC + wx;
        for (int c = 0; c < CCH; c++) {
            const float* qs = base0 + c*NPOS;
            float n[25];
            #pragma unroll
            for (int j = 0; j < 5; j++)
                #pragma unroll
                for (int i = 0; i < 5; i++)
                    n[j*5+i] = qs[j*WC + i];
            float q = n[12];
            #pragma unroll
            for (int k = 0; k < 25; k++)
                A[k] += q * n[k];
        }
        __syncthreads();
    }

    // ---- softmax over 25 neighbors ----
    {
        float m = A[0];
        #pragma unroll
        for (int k = 1; k < 25; k++) m = fmaxf(m, A[k]);
        float sum = 0.f;
        #pragma unroll
        for (int k = 0; k < 25; k++) { A[k] = __expf(A[k] - m); sum += A[k]; }
        float inv = 1.f/sum;
        #pragma unroll
        for (int k = 0; k < 25; k++) A[k] *= inv;
    }

    // ---- aggregate: two 32-channel chunks ----
    const float* Vb = V + (size_t)b*CHW;
    float* Ob = O + (size_t)b*CHW + (h0 + hy)*128 + (w0 + wx);
    #pragma unroll
    for (int ck = 0; ck < 2; ck++) {
        load_halo_chunk(Vb + ck*CCH*HW, s, tid, h0, w0);
        __syncthreads();

        const float* base0 = s + hy*WC + wx;
        for (int c = 0; c < CCH; c++) {
            const float* vs = base0 + c*NPOS;
            float o = 0.f;
            #pragma unroll
            for (int j = 0; j < 5; j++)
                #pragma unroll
                for (int i = 0; i < 5; i++)
                    o += A[j*5+i] * vs[j*WC + i];
            Ob[(size_t)(ck*CCH + c)*HW] = o;
        }
        __syncthreads();
    }
}

// ---------------------------------------------------------------------------
extern "C" void kernel_launch(void* const* d_in, const int* in_sizes, int n_in,
                              void* d_out, int out_size)
{
    const float* x  = (const float*)d_in[0];
    const float* y  = (const float*)d_in[1];
    const float* wx = (const float*)d_in[2];
    const float* bx = (const float*)d_in[3];
    const float* wy = (const float*)d_in[4];
    const float* by = (const float*)d_in[5];
    const float* wo = (const float*)d_in[6];
    const float* bo = (const float*)d_in[7];
    float* out = (float*)d_out;

    void *pQ, *pV, *pO;
    cudaGetSymbolAddress(&pQ, g_Q);
    cudaGetSymbolAddress(&pV, g_V);
    cudaGetSymbolAddress(&pO, g_O);

    cudaFuncSetAttribute(qv_conv_kernel,  cudaFuncAttributeMaxDynamicSharedMemorySize, CONV_SMEM);
    cudaFuncSetAttribute(out_conv_kernel, cudaFuncAttributeMaxDynamicSharedMemorySize, CONV_SMEM);
    cudaFuncSetAttribute(attn_kernel,     cudaFuncAttributeMaxDynamicSharedMemorySize, ATTN_SMEM);

    // q = wy @ y + by ; v = wx @ x + bx  (one fused launch, gridDim.y selects)
    qv_conv_kernel<<<dim3(NPIX/128, 2), 256, CONV_SMEM>>>(
        x, y, wx, bx, wy, by, (float*)pQ, (float*)pV);

    // scores + softmax + aggregate
    attn_kernel<<<dim3(128/WT, 128/HT, 4), 512, ATTN_SMEM>>>(
        (const float*)pQ, (const float*)pV, (float*)pO);

    // out = wo @ O + bo + x
    out_conv_kernel<<<NPIX/128, 256, CONV_SMEM>>>((const float*)pO, wo, bo, x, out);
}

// round 12
// speedup vs baseline: 1.0206x; 1.0017x over previous
#include <cuda_runtime.h>
#include <cstdint>

#define HW   (128*128)        // 16384 pixels per (b,c) plane
#define CHW  (64*HW)          // one batch image, 64 channels
#define NPIX (4*HW)           // total pixels across batch

// Scratch tensors (allocation-free rule: __device__ globals)
__device__ float g_Q[4*CHW];
__device__ float g_V[4*CHW];
__device__ float g_O[4*CHW];

// ---------------------------------------------------------------------------
// TF32 tensor-core helpers (legacy mma.sync — PTX sm_80+, no arch suffix)
// ---------------------------------------------------------------------------
__device__ __forceinline__ uint32_t cvt_tf32(float x) {
    uint32_t r;
    asm("cvt.rna.tf32.f32 %0, %1;" : "=r"(r) : "f"(x));
    return r;
}

__device__ __forceinline__ void mma_tf32(float* d, const uint32_t* a,
                                         uint32_t b0, uint32_t b1) {
    asm volatile(
        "mma.sync.aligned.m16n8k8.row.col.f32.tf32.tf32.f32 "
        "{%0,%1,%2,%3}, {%4,%5,%6,%7}, {%8,%9}, {%0,%1,%2,%3};\n"
        : "+f"(d[0]), "+f"(d[1]), "+f"(d[2]), "+f"(d[3])
        : "r"(a[0]), "r"(a[1]), "r"(a[2]), "r"(a[3]), "r"(b0), "r"(b1));
}

// ---------------------------------------------------------------------------
// conv1x1 via TF32 mma.sync, 3-pass fp32-split (ah*bh + al*bh + ah*bl).
// Per CTA: D[128px, 64f] = A[128px, 64c] * B[64f, 64c]^T, 256 threads, 8 warps.
// ALL tf32 conversion hoisted out of the mainloop:
//  - B pre-split into per-lane fragment layout Bf_h/Bf_l (uint2 -> 1 LDS.64)
//  - A smem columns permuted so each fragment pair is one LDS.64
// Mainloop per warp per kb: 2 A-LDS.64 + 8 cvt/sub + 16 B-LDS.64 + 24 mma.
// Epilogue: D staged through smem [f][132] -> coalesced float4 STG + bias/resid.
// ---------------------------------------------------------------------------
#define AS_STR 66
#define DS_STR 132
// floats: As 128*66 = 8448, Bf_h/Bf_l 2048 uint2 = 8192 floats, bias 64
#define CONV_SMEM ((8448 + 8192 + 64) * 4)   // 66816 B

__device__ __forceinline__ void conv_mma_body(
    const float* __restrict__ in, const float* __restrict__ w,
    const float* __restrict__ bias, const float* __restrict__ resid,
    float* __restrict__ out)
{
    extern __shared__ float sm[];
    float* As   = sm;                          // [128][66], permuted columns
    uint2* Bf_h = (uint2*)(sm + 8448);         // [64 combos][32 lanes]
    uint2* Bf_l = (uint2*)(sm + 8448 + 4096);
    float* bs   = sm + 8448 + 8192;            // [64]

    int tid = threadIdx.x;

    // ---- pre-split B into mma fragment layout (once per CTA) ----
    // combo = kb*8+nb ; lane -> g = lane>>2, t = lane&3
    // b0 = B[f=nb*8+g][c=kb*8+t], b1 = same с+4
    #pragma unroll
    for (int e = tid; e < 2048; e += 256) {
        int combo = e >> 5, ln = e & 31;
        int kb = combo >> 3, nb = combo & 7;
        int g = ln >> 2, t = ln & 3;
        int f = nb*8 + g;
        float v0 = w[f*64 + kb*8 + t];
        float v1 = w[f*64 + kb*8 + t + 4];
        uint32_t h0 = cvt_tf32(v0), h1 = cvt_tf32(v1);
        Bf_h[e] = make_uint2(h0, h1);
        Bf_l[e] = make_uint2(__float_as_uint(v0 - __uint_as_float(h0)),
                             __float_as_uint(v1 - __uint_as_float(h1)));
    }
    if (tid < 64) bs[tid] = bias[tid];

    int pix0 = blockIdx.x * 128;       // 16384 % 128 == 0
    int b    = pix0 >> 14;
    int p    = pix0 & (HW - 1);
    const float* inp = in + (size_t)b*CHW + p;

    // ---- load A transposed to [px][col'] with pairing permutation ----
    // col'(c): keep 8-block, cc = c&7 -> cc' = (cc&3)*2 + (cc>>2)
    // so (t, t+4) land adjacent -> fragment pair = one LDS.64
    for (int i = tid; i < 8192; i += 256) {
        int c = i >> 7, px = i & 127;
        int cc = c & 7;
        int colp = (c & ~7) | (((cc & 3) << 1) | (cc >> 2));
        As[px*AS_STR + colp] = inp[c*HW + px];   // LDG coalesced over px
    }
    __syncthreads();

    int wp   = tid >> 5;       // warp id: px rows 16*wp .. 16*wp+15
    int lane = tid & 31;
    int g    = lane >> 2;      // group 0..7
    int t    = lane & 3;       // thread-in-group 0..3

    float acc[8][4];
    #pragma unroll
    for (int nb = 0; nb < 8; nb++)
        #pragma unroll
        for (int j = 0; j < 4; j++) acc[nb][j] = 0.f;

    const float* ap0 = As + (16*wp + g)*AS_STR + 2*t;       // row g
    const float* ap1 = ap0 + 8*AS_STR;                      // row g+8

    #pragma unroll 2
    for (int kb = 0; kb < 8; kb++) {
        // A fragment: {a0,a1,a2,a3} = rows(g,g+8) x cols(t,t+4)
        float2 pa0 = *(const float2*)(ap0 + kb*8);   // a0 (col t), a2 (col t+4)
        float2 pa1 = *(const float2*)(ap1 + kb*8);   // a1,        a3
        uint32_t ah[4], al[4];
        ah[0] = cvt_tf32(pa0.x); al[0] = __float_as_uint(pa0.x - __uint_as_float(ah[0]));
        ah[1] = cvt_tf32(pa1.x); al[1] = __float_as_uint(pa1.x - __uint_as_float(ah[1]));
        ah[2] = cvt_tf32(pa0.y); al[2] = __float_as_uint(pa0.y - __uint_as_float(ah[2]));
        ah[3] = cvt_tf32(pa1.y); al[3] = __float_as_uint(pa1.y - __uint_as_float(ah[3]));

        const uint2* bh = Bf_h + kb*8*32 + lane;
        const uint2* bl = Bf_l + kb*8*32 + lane;
        #pragma unroll
        for (int nb = 0; nb < 8; nb++) {
            uint2 h = bh[nb*32];
            uint2 l = bl[nb*32];
            mma_tf32(acc[nb], ah, h.x, h.y);   // hi*hi
            mma_tf32(acc[nb], al, h.x, h.y);   // lo*hi
            mma_tf32(acc[nb], ah, l.x, l.y);   // hi*lo
        }
    }
    __syncthreads();

    // ---- stage D to smem as [f][px] (stride 132) ----
    float* Ds = sm;                    // [64][132] = 8448 floats (fits in As)
    #pragma unroll
    for (int nb = 0; nb < 8; nb++) {
        int f0 = nb*8 + 2*t;           // cols 2t, 2t+1 of this n-block
        int r0 = 16*wp + g;            // rows g, g+8
        Ds[f0*DS_STR + r0]           = acc[nb][0];
        Ds[(f0+1)*DS_STR + r0]       = acc[nb][1];
        Ds[f0*DS_STR + r0 + 8]       = acc[nb][2];
        Ds[(f0+1)*DS_STR + r0 + 8]   = acc[nb][3];
    }
    __syncthreads();

    // ---- coalesced output: warp wp covers f = wp*8 + r, lanes cover px ----
    float* outp = out + (size_t)b*CHW + p;
    const float* rp = resid ? (resid + (size_t)b*CHW + p) : nullptr;
    #pragma unroll
    for (int r = 0; r < 8; r++) {
        int f = wp*8 + r;
        float4 v = *(const float4*)(Ds + f*DS_STR + lane*4);
        float bv = bs[f];
        v.x += bv; v.y += bv; v.z += bv; v.w += bv;
        if (rp) {
            float4 rv = *(const float4*)(rp + (size_t)f*HW + lane*4);
            v.x += rv.x; v.y += rv.y; v.z += rv.z; v.w += rv.w;
        }
        *(float4*)(outp + (size_t)f*HW + lane*4) = v;
    }
}

__global__ void __launch_bounds__(256, 2) qv_conv_kernel(
    const float* __restrict__ x,  const float* __restrict__ y,
    const float* __restrict__ wx, const float* __restrict__ bx,
    const float* __restrict__ wy, const float* __restrict__ by,
    float* __restrict__ Q, float* __restrict__ V)
{
    if (blockIdx.y == 0) conv_mma_body(y, wy, by, nullptr, Q);
    else                 conv_mma_body(x, wx, bx, nullptr, V);
}

__global__ void __launch_bounds__(256, 2) out_conv_kernel(
    const float* __restrict__ in, const float* __restrict__ w,
    const float* __restrict__ bias, const float* __restrict__ resid,
    float* __restrict__ out)
{
    conv_mma_body(in, w, bias, resid, out);
}

// ---------------------------------------------------------------------------
// Local attention (5x5 window, zero-padded) — R7/R8 high-occupancy version
// (measured-good). 512 threads, 1 px/thread, two 32-channel chunks, 92KB smem.
// ---------------------------------------------------------------------------
#define HT 16
#define WT 32
#define HR (HT + 4)     // 20
#define WC (WT + 4)     // 36
#define NPOS (HR * WC)  // 720
#define CCH 32          // channels per chunk
#define ATTN_SMEM (CCH*NPOS*4)   // 92160 B

__device__ __forceinline__ void load_halo_chunk(
    const float* __restrict__ src,
    float* __restrict__ s, int tid, int h0, int w0)
{
    #pragma unroll 5
    for (int i = tid; i < CCH*NPOS; i += 512) {
        int c   = i / NPOS;
        int pos = i - c*NPOS;
        int r   = pos / WC;
        int col = pos - r*WC;
        int gh  = h0 + r - 2;
        int gw  = w0 + col - 2;
        float v = 0.f;
        if ((unsigned)gh < 128u && (unsigned)gw < 128u)
            v = src[c*HW + gh*128 + gw];
        s[i] = v;
    }
}

__global__ void __launch_bounds__(512, 1) attn_kernel(
    const float* __restrict__ Q, const float* __restrict__ V,
    float* __restrict__ O)
{
    extern __shared__ float s[];   // [CCH][NPOS]

    int tid = threadIdx.x;
    int wx  = tid & 31;
    int hy  = tid >> 5;
    int b   = blockIdx.z;
    int h0  = blockIdx.y * HT;
    int w0  = blockIdx.x * WT;

    float A[25];
    #pragma unroll
    for (int k = 0; k < 25; k++) A[k] = 0.f;

    // ---- scores: two 32-channel chunks ----
    const float* Qb = Q + (size_t)b*CHW;
    #pragma unroll
    for (int ck = 0; ck < 2; ck++) {
        load_halo_chunk(Qb + ck*CCH*HW, s, tid, h0, w0);
        __syncthreads();

        const float* base0 = s + hy*WC + wx;
        for (int c = 0; c < CCH; c++) {
            const float* qs = base0 + c*NPOS;
            float n[25];
            #pragma unroll
            for (int j = 0; j < 5; j++)
                #pragma unroll
                for (int i = 0; i < 5; i++)
                    n[j*5+i] = qs[j*WC + i];
            float q = n[12];
            #pragma unroll
            for (int k = 0; k < 25; k++)
                A[k] += q * n[k];
        }
        __syncthreads();
    }

    // ---- softmax over 25 neighbors ----
    {
        float m = A[0];
        #pragma unroll
        for (int k = 1; k < 25; k++) m = fmaxf(m, A[k]);
        float sum = 0.f;
        #pragma unroll
        for (int k = 0; k < 25; k++) { A[k] = __expf(A[k] - m); sum += A[k]; }
        float inv = 1.f/sum;
        #pragma unroll
        for (int k = 0; k < 25; k++) A[k] *= inv;
    }

    // ---- aggregate: two 32-channel chunks ----
    const float* Vb = V + (size_t)b*CHW;
    float* Ob = O + (size_t)b*CHW + (h0 + hy)*128 + (w0 + wx);
    #pragma unroll
    for (int ck = 0; ck < 2; ck++) {
        load_halo_chunk(Vb + ck*CCH*HW, s, tid, h0, w0);
        __syncthreads();

        const float* base0 = s + hy*WC + wx;
        for (int c = 0; c < CCH; c++) {
            const float* vs = base0 + c*NPOS;
            float o = 0.f;
            #pragma unroll
            for (int j = 0; j < 5; j++)
                #pragma unroll
                for (int i = 0; i < 5; i++)
                    o += A[j*5+i] * vs[j*WC + i];
            Ob[(size_t)(ck*CCH + c)*HW] = o;
        }
        __syncthreads();
    }
}

// ---------------------------------------------------------------------------
extern "C" void kernel_launch(void* const* d_in, const int* in_sizes, int n_in,
                              void* d_out, int out_size)
{
    const float* x  = (const float*)d_in[0];
    const float* y  = (const float*)d_in[1];
    const float* wx = (const float*)d_in[2];
    const float* bx = (const float*)d_in[3];
    const float* wy = (const float*)d_in[4];
    const float* by = (const float*)d_in[5];
    const float* wo = (const float*)d_in[6];
    const float* bo = (const float*)d_in[7];
    float* out = (float*)d_out;

    void *pQ, *pV, *pO;
    cudaGetSymbolAddress(&pQ, g_Q);
    cudaGetSymbolAddress(&pV, g_V);
    cudaGetSymbolAddress(&pO, g_O);

    cudaFuncSetAttribute(qv_conv_kernel,  cudaFuncAttributeMaxDynamicSharedMemorySize, CONV_SMEM);
    cudaFuncSetAttribute(out_conv_kernel, cudaFuncAttributeMaxDynamicSharedMemorySize, CONV_SMEM);
    cudaFuncSetAttribute(attn_kernel,     cudaFuncAttributeMaxDynamicSharedMemorySize, ATTN_SMEM);

    // q = wy @ y + by ; v = wx @ x + bx  (one fused launch, gridDim.y selects)
    qv_conv_kernel<<<dim3(NPIX/128, 2), 256, CONV_SMEM>>>(
        x, y, wx, bx, wy, by, (float*)pQ, (float*)pV);

    // scores + softmax + aggregate
    attn_kernel<<<dim3(128/WT, 128/HT, 4), 512, ATTN_SMEM>>>(
        (const float*)pQ, (const float*)pV, (float*)pO);

    // out = wo @ O + bo + x
    out_conv_kernel<<<NPIX/128, 256, CONV_SMEM>>>((const float*)pO, wo, bo, x, out);
}

// round 13
// speedup vs baseline: 1.1168x; 1.0942x over previous
#include <cuda_runtime.h>
#include <cuda_bf16.h>
#include <cstdint>

#define HW   (128*128)        // 16384 pixels per (b,c) plane
#define CHW  (64*HW)          // one batch image, 64 channels
#define NPIX (4*HW)           // total pixels across batch

// Scratch tensors (allocation-free rule: __device__ globals)
__device__ float g_Q[4*CHW];
__device__ float g_V[4*CHW];
__device__ float g_O[4*CHW];

// ---------------------------------------------------------------------------
// bf16 tensor-core helpers (legacy mma.sync m16n8k16 — PTX sm_80+)
// ---------------------------------------------------------------------------
__device__ __forceinline__ uint32_t pack_bf16(float lo, float hi) {
    // low 16 bits = element with LOWER k index
    __nv_bfloat16 a = __float2bfloat16(lo);
    __nv_bfloat16 b = __float2bfloat16(hi);
    uint16_t ua = *(uint16_t*)&a, ub = *(uint16_t*)&b;
    return (uint32_t)ua | ((uint32_t)ub << 16);
}
__device__ __forceinline__ float bf16_hi_part(float v, float& rem) {
    __nv_bfloat16 h = __float2bfloat16(v);
    float hf = __bfloat162float(h);
    rem = v - hf;
    return hf;
}

__device__ __forceinline__ void mma_bf16(float* d,
                                         uint32_t a0, uint32_t a1,
                                         uint32_t a2, uint32_t a3,
                                         uint32_t b0, uint32_t b1) {
    asm volatile(
        "mma.sync.aligned.m16n8k16.row.col.f32.bf16.bf16.f32 "
        "{%0,%1,%2,%3}, {%4,%5,%6,%7}, {%8,%9}, {%0,%1,%2,%3};\n"
        : "+f"(d[0]), "+f"(d[1]), "+f"(d[2]), "+f"(d[3])
        : "r"(a0), "r"(a1), "r"(a2), "r"(a3), "r"(b0), "r"(b1));
}

// ---------------------------------------------------------------------------
// conv1x1 via bf16 m16n8k16 mma.sync, 3-pass split (ah*bh + al*bh + ah*bl).
// Per CTA: D[128px, 64f] = A[128px, 64c] * B[64f, 64c]^T, 256 threads, 8 warps.
// Prolog converts EVERYTHING to packed bf16x2 in smem:
//   Ah/Al[px][pair'] uint32 (pairing permutation -> fragment pair = 1 LDS.64,
//                            stride 40 -> max 2-way bank conflicts)
//   BfH/BfL[combo][lane] uint2 (per-lane fragment layout -> 1 LDS.64)
// Mainloop per warp: 4 kb x (4 A-LDS.64 + 16 B-LDS.64 + 24 mma), zero cvt.
// Epilogue: D staged through smem [f][132] -> coalesced float4 STG + bias/resid.
// ---------------------------------------------------------------------------
#define AH_STR 40
#define DS_STR 132
// words: Ah 5120, Al 5120, BfH 2048, BfL 2048, bias 64 = 14400 words
#define CONV_SMEM (14400 * 4)   // 57600 B

__device__ __forceinline__ void conv_mma_body(
    const float* __restrict__ in, const float* __restrict__ w,
    const float* __restrict__ bias, const float* __restrict__ resid,
    float* __restrict__ out)
{
    extern __shared__ float sm[];
    uint32_t* Ah  = (uint32_t*)sm;             // [128][40] packed bf16x2 pairs
    uint32_t* Al  = (uint32_t*)sm + 5120;
    uint2*    BfH = (uint2*)((uint32_t*)sm + 10240);   // [32 combos][32 lanes]
    uint2*    BfL = (uint2*)((uint32_t*)sm + 12288);
    float*    bs  = sm + 14336;                // [64]

    int tid = threadIdx.x;

    // ---- pre-split B into bf16 fragment layout (once per CTA) ----
    // combo = kb*8+nb (kb 0..3); lane -> g = ln>>2, t = ln&3
    // b0 = {B[f][kb*16+2t], B[f][kb*16+2t+1]}, b1 = same +8, f = nb*8+g
    #pragma unroll
    for (int e = tid; e < 1024; e += 256) {
        int combo = e >> 5, ln = e & 31;
        int kb = combo >> 3, nb = combo & 7;
        int g = ln >> 2, t = ln & 3;
        const float* wf = w + (nb*8 + g)*64 + kb*16 + 2*t;
        float r0, r1, r2, r3;
        float h0 = bf16_hi_part(wf[0], r0);
        float h1 = bf16_hi_part(wf[1], r1);
        float h2 = bf16_hi_part(wf[8], r2);
        float h3 = bf16_hi_part(wf[9], r3);
        BfH[e] = make_uint2(pack_bf16(h0, h1), pack_bf16(h2, h3));
        BfL[e] = make_uint2(pack_bf16(r0, r1), pack_bf16(r2, r3));
    }
    if (tid < 64) bs[tid] = bias[tid];

    int pix0 = blockIdx.x * 128;       // 16384 % 128 == 0
    int b    = pix0 >> 14;
    int p    = pix0 & (HW - 1);
    const float* inp = in + (size_t)b*CHW + p;

    // ---- load A, split+pack to bf16x2 k-pairs with pairing permutation ----
    // pair pc = c/2 (0..31); cc = pc&7 -> cc' = ((cc&3)<<1)|(cc>>2)
    // so fragment pairs (t, t+4) land adjacent -> one LDS.64
    #pragma unroll
    for (int i = tid; i < 4096; i += 256) {
        int px = i & 127, pc = i >> 7;
        float v0 = inp[(2*pc)*HW + px];        // coalesced over px
        float v1 = inp[(2*pc + 1)*HW + px];
        float r0, r1;
        float h0 = bf16_hi_part(v0, r0);
        float h1 = bf16_hi_part(v1, r1);
        int cc = pc & 7;
        int col = (pc & ~7) | (((cc & 3) << 1) | (cc >> 2));
        Ah[px*AH_STR + col] = pack_bf16(h0, h1);
        Al[px*AH_STR + col] = pack_bf16(r0, r1);
    }
    __syncthreads();

    int wp   = tid >> 5;       // warp id: px rows 16*wp .. 16*wp+15
    int lane = tid & 31;
    int g    = lane >> 2;      // group 0..7
    int t    = lane & 3;       // thread-in-group 0..3

    float acc[8][4];
    #pragma unroll
    for (int nb = 0; nb < 8; nb++)
        #pragma unroll
        for (int j = 0; j < 4; j++) acc[nb][j] = 0.f;

    const uint32_t* ahp = Ah + (16*wp + g)*AH_STR + 2*t;   // row g
    const uint32_t* alp = Al + (16*wp + g)*AH_STR + 2*t;

    #pragma unroll
    for (int kb = 0; kb < 4; kb++) {
        // A fragments: row g -> (a0, a2); row g+8 -> (a1, a3)
        uint2 rgh  = *(const uint2*)(ahp + kb*8);
        uint2 rg8h = *(const uint2*)(ahp + 8*AH_STR + kb*8);
        uint2 rgl  = *(const uint2*)(alp + kb*8);
        uint2 rg8l = *(const uint2*)(alp + 8*AH_STR + kb*8);

        const uint2* bh = BfH + kb*8*32 + lane;
        const uint2* bl = BfL + kb*8*32 + lane;
        #pragma unroll
        for (int nb = 0; nb < 8; nb++) {
            uint2 h = bh[nb*32];
            uint2 l = bl[nb*32];
            mma_bf16(acc[nb], rgh.x, rg8h.x, rgh.y, rg8h.y, h.x, h.y);  // hi*hi
            mma_bf16(acc[nb], rgl.x, rg8l.x, rgl.y, rg8l.y, h.x, h.y);  // lo*hi
            mma_bf16(acc[nb], rgh.x, rg8h.x, rgh.y, rg8h.y, l.x, l.y);  // hi*lo
        }
    }
    __syncthreads();

    // ---- stage D to smem as [f][px] (stride 132) ----
    float* Ds = sm;                    // [64][132] = 8448 words (fits in Ah/Al)
    #pragma unroll
    for (int nb = 0; nb < 8; nb++) {
        int f0 = nb*8 + 2*t;           // cols 2t, 2t+1 of this n-block
        int r0 = 16*wp + g;            // rows g, g+8
        Ds[f0*DS_STR + r0]           = acc[nb][0];
        Ds[(f0+1)*DS_STR + r0]       = acc[nb][1];
        Ds[f0*DS_STR + r0 + 8]       = acc[nb][2];
        Ds[(f0+1)*DS_STR + r0 + 8]   = acc[nb][3];
    }
    __syncthreads();

    // ---- coalesced output: warp wp covers f = wp*8 + r, lanes cover px ----
    float* outp = out + (size_t)b*CHW + p;
    const float* rp = resid ? (resid + (size_t)b*CHW + p) : nullptr;
    #pragma unroll
    for (int r = 0; r < 8; r++) {
        int f = wp*8 + r;
        float4 v = *(const float4*)(Ds + f*DS_STR + lane*4);
        float bv = bs[f];
        v.x += bv; v.y += bv; v.z += bv; v.w += bv;
        if (rp) {
            float4 rv = *(const float4*)(rp + (size_t)f*HW + lane*4);
            v.x += rv.x; v.y += rv.y; v.z += rv.z; v.w += rv.w;
        }
        *(float4*)(outp + (size_t)f*HW + lane*4) = v;
    }
}

__global__ void __launch_bounds__(256, 2) qv_conv_kernel(
    const float* __restrict__ x,  const float* __restrict__ y,
    const float* __restrict__ wx, const float* __restrict__ bx,
    const float* __restrict__ wy, const float* __restrict__ by,
    float* __restrict__ Q, float* __restrict__ V)
{
    if (blockIdx.y == 0) conv_mma_body(y, wy, by, nullptr, Q);
    else                 conv_mma_body(x, wx, bx, nullptr, V);
}

__global__ void __launch_bounds__(256, 2) out_conv_kernel(
    const float* __restrict__ in, const float* __restrict__ w,
    const float* __restrict__ bias, const float* __restrict__ resid,
    float* __restrict__ out)
{
    conv_mma_body(in, w, bias, resid, out);
}

// ---------------------------------------------------------------------------
// Local attention (5x5 window, zero-padded) — R7/R8 high-occupancy version
// (measured-good). 512 threads, 1 px/thread, two 32-channel chunks, 92KB smem.
// ---------------------------------------------------------------------------
#define HT 16
#define WT 32
#define HR (HT + 4)     // 20
#define WC (WT + 4)     // 36
#define NPOS (HR * WC)  // 720
#define CCH 32          // channels per chunk
#define ATTN_SMEM (CCH*NPOS*4)   // 92160 B

__device__ __forceinline__ void load_halo_chunk(
    const float* __restrict__ src,
    float* __restrict__ s, int tid, int h0, int w0)
{
    #pragma unroll 5
    for (int i = tid; i < CCH*NPOS; i += 512) {
        int c   = i / NPOS;
        int pos = i - c*NPOS;
        int r   = pos / WC;
        int col = pos - r*WC;
        int gh  = h0 + r - 2;
        int gw  = w0 + col - 2;
        float v = 0.f;
        if ((unsigned)gh < 128u && (unsigned)gw < 128u)
            v = src[c*HW + gh*128 + gw];
        s[i] = v;
    }
}

__global__ void __launch_bounds__(512, 1) attn_kernel(
    const float* __restrict__ Q, const float* __restrict__ V,
    float* __restrict__ O)
{
    extern __shared__ float s[];   // [CCH][NPOS]

    int tid = threadIdx.x;
    int wx  = tid & 31;
    int hy  = tid >> 5;
    int b   = blockIdx.z;
    int h0  = blockIdx.y * HT;
    int w0  = blockIdx.x * WT;

    float A[25];
    #pragma unroll
    for (int k = 0; k < 25; k++) A[k] = 0.f;

    // ---- scores: two 32-channel chunks ----
    const float* Qb = Q + (size_t)b*CHW;
    #pragma unroll
    for (int ck = 0; ck < 2; ck++) {
        load_halo_chunk(Qb + ck*CCH*HW, s, tid, h0, w0);
        __syncthreads();

        const float* base0 = s + hy*WC + wx;
        for (int c = 0; c < CCH; c++) {
            const float* qs = base0 + c*NPOS;
            float n[25];
            #pragma unroll
            for (int j = 0; j < 5; j++)
                #pragma unroll
                for (int i = 0; i < 5; i++)
                    n[j*5+i] = qs[j*WC + i];
            float q = n[12];
            #pragma unroll
            for (int k = 0; k < 25; k++)
                A[k] += q * n[k];
        }
        __syncthreads();
    }

    // ---- softmax over 25 neighbors ----
    {
        float m = A[0];
        #pragma unroll
        for (int k = 1; k < 25; k++) m = fmaxf(m, A[k]);
        float sum = 0.f;
        #pragma unroll
        for (int k = 0; k < 25; k++) { A[k] = __expf(A[k] - m); sum += A[k]; }
        float inv = 1.f/sum;
        #pragma unroll
        for (int k = 0; k < 25; k++) A[k] *= inv;
    }

    // ---- aggregate: two 32-channel chunks ----
    const float* Vb = V + (size_t)b*CHW;
    float* Ob = O + (size_t)b*CHW + (h0 + hy)*128 + (w0 + wx);
    #pragma unroll
    for (int ck = 0; ck < 2; ck++) {
        load_halo_chunk(Vb + ck*CCH*HW, s, tid, h0, w0);
        __syncthreads();

        const float* base0 = s + hy*WC + wx;
        for (int c = 0; c < CCH; c++) {
            const float* vs = base0 + c*NPOS;
            float o = 0.f;
            #pragma unroll
            for (int j = 0; j < 5; j++)
                #pragma unroll
                for (int i = 0; i < 5; i++)
                    o += A[j*5+i] * vs[j*WC + i];
            Ob[(size_t)(ck*CCH + c)*HW] = o;
        }
        __syncthreads();
    }
}

// ---------------------------------------------------------------------------
extern "C" void kernel_launch(void* const* d_in, const int* in_sizes, int n_in,
                              void* d_out, int out_size)
{
    const float* x  = (const float*)d_in[0];
    const float* y  = (const float*)d_in[1];
    const float* wx = (const float*)d_in[2];
    const float* bx = (const float*)d_in[3];
    const float* wy = (const float*)d_in[4];
    const float* by = (const float*)d_in[5];
    const float* wo = (const float*)d_in[6];
    const float* bo = (const float*)d_in[7];
    float* out = (float*)d_out;

    void *pQ, *pV, *pO;
    cudaGetSymbolAddress(&pQ, g_Q);
    cudaGetSymbolAddress(&pV, g_V);
    cudaGetSymbolAddress(&pO, g_O);

    cudaFuncSetAttribute(qv_conv_kernel,  cudaFuncAttributeMaxDynamicSharedMemorySize, CONV_SMEM);
    cudaFuncSetAttribute(out_conv_kernel, cudaFuncAttributeMaxDynamicSharedMemorySize, CONV_SMEM);
    cudaFuncSetAttribute(attn_kernel,     cudaFuncAttributeMaxDynamicSharedMemorySize, ATTN_SMEM);

    // q = wy @ y + by ; v = wx @ x + bx  (one fused launch, gridDim.y selects)
    qv_conv_kernel<<<dim3(NPIX/128, 2), 256, CONV_SMEM>>>(
        x, y, wx, bx, wy, by, (float*)pQ, (float*)pV);

    // scores + softmax + aggregate
    attn_kernel<<<dim3(128/WT, 128/HT, 4), 512, ATTN_SMEM>>>(
        (const float*)pQ, (const float*)pV, (float*)pO);

    // out = wo @ O + bo + x
    out_conv_kernel<<<NPIX/128, 256, CONV_SMEM>>>((const float*)pO, wo, bo, x, out);
}

// round 15
// speedup vs baseline: 1.2308x; 1.1022x over previous
#include <cuda_runtime.h>
#include <cuda_bf16.h>
#include <cstdint>

#define HW   (128*128)        // 16384 pixels per (b,c) plane
#define CHW  (64*HW)          // one batch image, 64 channels
#define NPIX (4*HW)           // total pixels across batch

// Scratch tensors (allocation-free rule: __device__ globals)
__device__ float g_Q[4*CHW];
__device__ float g_V[4*CHW];
__device__ float g_O[4*CHW];

// ---------------------------------------------------------------------------
// bf16 tensor-core helpers (legacy mma.sync m16n8k16 — PTX sm_80+)
// ---------------------------------------------------------------------------
__device__ __forceinline__ uint32_t pack_bf16(float lo, float hi) {
    __nv_bfloat16 a = __float2bfloat16(lo);
    __nv_bfloat16 b = __float2bfloat16(hi);
    uint16_t ua = *(uint16_t*)&a, ub = *(uint16_t*)&b;
    return (uint32_t)ua | ((uint32_t)ub << 16);
}
__device__ __forceinline__ float bf16_hi_part(float v, float& rem) {
    __nv_bfloat16 h = __float2bfloat16(v);
    float hf = __bfloat162float(h);
    rem = v - hf;
    return hf;
}

__device__ __forceinline__ void mma_bf16(float* d,
                                         uint32_t a0, uint32_t a1,
                                         uint32_t a2, uint32_t a3,
                                         uint32_t b0, uint32_t b1) {
    asm volatile(
        "mma.sync.aligned.m16n8k16.row.col.f32.bf16.bf16.f32 "
        "{%0,%1,%2,%3}, {%4,%5,%6,%7}, {%8,%9}, {%0,%1,%2,%3};\n"
        : "+f"(d[0]), "+f"(d[1]), "+f"(d[2]), "+f"(d[3])
        : "r"(a0), "r"(a1), "r"(a2), "r"(a3), "r"(b0), "r"(b1));
}

// ---------------------------------------------------------------------------
// Persistent conv1x1 via bf16 m16n8k16, 3-pass split, 4 tiles per CTA,
// double-buffered A with register prefetch (LDG latency hidden behind mma).
//  - B split/packed into fragment layout ONCE per CTA
//  - A stride 42 (even -> uint2-aligned; 2-way bank conflicts, was 8-way)
//  - epilogue Ds reuses the just-consumed A buffer
// smem words: Abuf[2][10752] (Ah 5376 + Al 5376), BfH/BfL 4096, bias 64
// ---------------------------------------------------------------------------
#define AH_STR 42
#define ABUF_W (128*AH_STR)          // 5376 words per array
#define DS_STR 132
#define TILES  4
#define NCTA   128                   // CTAs per conv job (128*4*128px = 65536)
#define CONV_SMEM ((2*2*ABUF_W + 4096 + 64) * 4)   // 102656 B

__device__ __forceinline__ void conv_mma_persistent(
    const float* __restrict__ in, const float* __restrict__ w,
    const float* __restrict__ bias, const float* __restrict__ resid,
    float* __restrict__ out)
{
    extern __shared__ float sm[];
    uint32_t* smw = (uint32_t*)sm;
    // buffer b: Ah at smw + b*2*ABUF_W, Al at +ABUF_W
    uint2* BfH = (uint2*)(smw + 4*ABUF_W);          // [32 combos][32 lanes]
    uint2* BfL = (uint2*)(smw + 4*ABUF_W + 2048);
    float* bs  = sm + 4*ABUF_W + 4096;              // [64]

    int tid = threadIdx.x;

    // ---- pre-split B into bf16 fragment layout (ONCE per CTA) ----
    #pragma unroll
    for (int e = tid; e < 1024; e += 256) {
        int combo = e >> 5, ln = e & 31;
        int kb = combo >> 3, nb = combo & 7;
        int g = ln >> 2, t = ln & 3;
        const float* wf = w + (nb*8 + g)*64 + kb*16 + 2*t;
        float r0, r1, r2, r3;
        float h0 = bf16_hi_part(wf[0], r0);
        float h1 = bf16_hi_part(wf[1], r1);
        float h2 = bf16_hi_part(wf[8], r2);
        float h3 = bf16_hi_part(wf[9], r3);
        BfH[e] = make_uint2(pack_bf16(h0, h1), pack_bf16(h2, h3));
        BfL[e] = make_uint2(pack_bf16(r0, r1), pack_bf16(r2, r3));
    }
    if (tid < 64) bs[tid] = bias[tid];

    int px  = tid & 127;           // pixel column this thread packs
    int pcb = tid >> 7;            // 0/1: pair-group base

    // ---- load tile 0 into buffer 0 ----
    {
        int pix0 = blockIdx.x * 128;
        int b = pix0 >> 14, p = pix0 & (HW - 1);
        const float* inp = in + (size_t)b*CHW + p;
        uint32_t* Ah = smw;
        uint32_t* Al = smw + ABUF_W;
        #pragma unroll
        for (int j = 0; j < 16; j++) {
            int pc = pcb + 2*j;
            float v0 = inp[(2*pc)*HW + px];
            float v1 = inp[(2*pc + 1)*HW + px];
            float r0, r1;
            float h0 = bf16_hi_part(v0, r0);
            float h1 = bf16_hi_part(v1, r1);
            int cc = pc & 7;
            int col = (pc & ~7) | (((cc & 3) << 1) | (cc >> 2));
            Ah[px*AH_STR + col] = pack_bf16(h0, h1);
            Al[px*AH_STR + col] = pack_bf16(r0, r1);
        }
    }
    __syncthreads();

    int wp   = tid >> 5;       // warp: px rows 16*wp .. 16*wp+15
    int lane = tid & 31;
    int g    = lane >> 2;
    int t4   = lane & 3;

    int cur = 0;
    #pragma unroll 1
    for (int t = 0; t < TILES; t++) {
        int pix0 = (blockIdx.x + NCTA*t) * 128;
        int b = pix0 >> 14, p = pix0 & (HW - 1);

        // ---- issue prefetch LDGs for next tile (results used after mma) ----
        float av0[16], av1[16];
        if (t < TILES-1) {
            int pix2 = (blockIdx.x + NCTA*(t+1)) * 128;
            int b2 = pix2 >> 14, p2 = pix2 & (HW - 1);
            const float* inp2 = in + (size_t)b2*CHW + p2;
            #pragma unroll
            for (int j = 0; j < 16; j++) {
                int pc = pcb + 2*j;
                av0[j] = inp2[(2*pc)*HW + px];
                av1[j] = inp2[(2*pc + 1)*HW + px];
            }
        }

        // ---- mma mainloop on buf[cur] ----
        uint32_t* Ah = smw + cur*2*ABUF_W;
        uint32_t* Al = Ah + ABUF_W;

        float acc[8][4];
        #pragma unroll
        for (int nb = 0; nb < 8; nb++)
            #pragma unroll
            for (int j = 0; j < 4; j++) acc[nb][j] = 0.f;

        const uint32_t* ahp = Ah + (16*wp + g)*AH_STR + 2*t4;
        const uint32_t* alp = Al + (16*wp + g)*AH_STR + 2*t4;

        #pragma unroll
        for (int kb = 0; kb < 4; kb++) {
            uint2 rgh  = *(const uint2*)(ahp + kb*8);
            uint2 rg8h = *(const uint2*)(ahp + 8*AH_STR + kb*8);
            uint2 rgl  = *(const uint2*)(alp + kb*8);
            uint2 rg8l = *(const uint2*)(alp + 8*AH_STR + kb*8);

            const uint2* bh = BfH + kb*8*32 + lane;
            const uint2* bl = BfL + kb*8*32 + lane;
            #pragma unroll
            for (int nb = 0; nb < 8; nb++) {
                uint2 h = bh[nb*32];
                uint2 l = bl[nb*32];
                mma_bf16(acc[nb], rgh.x, rg8h.x, rgh.y, rg8h.y, h.x, h.y);
                mma_bf16(acc[nb], rgl.x, rg8l.x, rgl.y, rg8l.y, h.x, h.y);
                mma_bf16(acc[nb], rgh.x, rg8h.x, rgh.y, rg8h.y, l.x, l.y);
            }
        }
        __syncthreads();   // all warps done reading buf[cur]

        // ---- convert+store prefetched A into the other buffer ----
        if (t < TILES-1) {
            uint32_t* Ah2 = smw + (cur^1)*2*ABUF_W;
            uint32_t* Al2 = Ah2 + ABUF_W;
            #pragma unroll
            for (int j = 0; j < 16; j++) {
                int pc = pcb + 2*j;
                float r0, r1;
                float h0 = bf16_hi_part(av0[j], r0);
                float h1 = bf16_hi_part(av1[j], r1);
                int cc = pc & 7;
                int col = (pc & ~7) | (((cc & 3) << 1) | (cc >> 2));
                Ah2[px*AH_STR + col] = pack_bf16(h0, h1);
                Al2[px*AH_STR + col] = pack_bf16(r0, r1);
            }
        }

        // ---- epilogue: stage D in buf[cur] (free now), then coalesced STG ----
        float* Ds = (float*)(smw + cur*2*ABUF_W);
        #pragma unroll
        for (int nb = 0; nb < 8; nb++) {
            int f0 = nb*8 + 2*t4;
            int r0 = 16*wp + g;
            Ds[f0*DS_STR + r0]         = acc[nb][0];
            Ds[(f0+1)*DS_STR + r0]     = acc[nb][1];
            Ds[f0*DS_STR + r0 + 8]     = acc[nb][2];
            Ds[(f0+1)*DS_STR + r0 + 8] = acc[nb][3];
        }
        __syncthreads();

        float* outp = out + (size_t)b*CHW + p;
        const float* rp = resid ? (resid + (size_t)b*CHW + p) : nullptr;
        #pragma unroll
        for (int r = 0; r < 8; r++) {
            int f = wp*8 + r;
            float4 v = *(const float4*)(Ds + f*DS_STR + lane*4);
            float bv = bs[f];
            v.x += bv; v.y += bv; v.z += bv; v.w += bv;
            if (rp) {
                float4 rv = *(const float4*)(rp + (size_t)f*HW + lane*4);
                v.x += rv.x; v.y += rv.y; v.z += rv.z; v.w += rv.w;
            }
            *(float4*)(outp + (size_t)f*HW + lane*4) = v;
        }
        __syncthreads();   // Ds reads + buf[nxt] writes complete
        cur ^= 1;
    }
}

__global__ void __launch_bounds__(256, 2) qv_conv_kernel(
    const float* __restrict__ x,  const float* __restrict__ y,
    const float* __restrict__ wx, const float* __restrict__ bx,
    const float* __restrict__ wy, const float* __restrict__ by,
    float* __restrict__ Q, float* __restrict__ V)
{
    if (blockIdx.y == 0) conv_mma_persistent(y, wy, by, nullptr, Q);
    else                 conv_mma_persistent(x, wx, bx, nullptr, V);
}

__global__ void __launch_bounds__(256, 2) out_conv_kernel(
    const float* __restrict__ in, const float* __restrict__ w,
    const float* __restrict__ bias, const float* __restrict__ resid,
    float* __restrict__ out)
{
    conv_mma_persistent(in, w, bias, resid, out);
}

// ---------------------------------------------------------------------------
// Local attention (5x5 window, zero-padded) — R7/R8 high-occupancy version
// (measured-good). 512 threads, 1 px/thread, two 32-channel chunks, 92KB smem.
// ---------------------------------------------------------------------------
#define HT 16
#define WT 32
#define HR (HT + 4)     // 20
#define WC (WT + 4)     // 36
#define NPOS (HR * WC)  // 720
#define CCH 32          // channels per chunk
#define ATTN_SMEM (CCH*NPOS*4)   // 92160 B

__device__ __forceinline__ void load_halo_chunk(
    const float* __restrict__ src,
    float* __restrict__ s, int tid, int h0, int w0)
{
    #pragma unroll 5
    for (int i = tid; i < CCH*NPOS; i += 512) {
        int c   = i / NPOS;
        int pos = i - c*NPOS;
        int r   = pos / WC;
        int col = pos - r*WC;
        int gh  = h0 + r - 2;
        int gw  = w0 + col - 2;
        float v = 0.f;
        if ((unsigned)gh < 128u && (unsigned)gw < 128u)
            v = src[c*HW + gh*128 + gw];
        s[i] = v;
    }
}

__global__ void __launch_bounds__(512, 1) attn_kernel(
    const float* __restrict__ Q, const float* __restrict__ V,
    float* __restrict__ O)
{
    extern __shared__ float s[];   // [CCH][NPOS]

    int tid = threadIdx.x;
    int wx  = tid & 31;
    int hy  = tid >> 5;
    int b   = blockIdx.z;
    int h0  = blockIdx.y * HT;
    int w0  = blockIdx.x * WT;

    float A[25];
    #pragma unroll
    for (int k = 0; k < 25; k++) A[k] = 0.f;

    // ---- scores: two 32-channel chunks ----
    const float* Qb = Q + (size_t)b*CHW;
    #pragma unroll
    for (int ck = 0; ck < 2; ck++) {
        load_halo_chunk(Qb + ck*CCH*HW, s, tid, h0, w0);
        __syncthreads();

        const float* base0 = s + hy*WC + wx;
        for (int c = 0; c < CCH; c++) {
            const float* qs = base0 + c*NPOS;
            float n[25];
            #pragma unroll
            for (int j = 0; j < 5; j++)
                #pragma unroll
                for (int i = 0; i < 5; i++)
                    n[j*5+i] = qs[j*WC + i];
            float q = n[12];
            #pragma unroll
            for (int k = 0; k < 25; k++)
                A[k] += q * n[k];
        }
        __syncthreads();
    }

    // ---- softmax over 25 neighbors ----
    {
        float m = A[0];
        #pragma unroll
        for (int k = 1; k < 25; k++) m = fmaxf(m, A[k]);
        float sum = 0.f;
        #pragma unroll
        for (int k = 0; k < 25; k++) { A[k] = __expf(A[k] - m); sum += A[k]; }
        float inv = 1.f/sum;
        #pragma unroll
        for (int k = 0; k < 25; k++) A[k] *= inv;
    }

    // ---- aggregate: two 32-channel chunks ----
    const float* Vb = V + (size_t)b*CHW;
    float* Ob = O + (size_t)b*CHW + (h0 + hy)*128 + (w0 + wx);
    #pragma unroll
    for (int ck = 0; ck < 2; ck++) {
        load_halo_chunk(Vb + ck*CCH*HW, s, tid, h0, w0);
        __syncthreads();

        const float* base0 = s + hy*WC + wx;
        for (int c = 0; c < CCH; c++) {
            const float* vs = base0 + c*NPOS;
            float o = 0.f;
            #pragma unroll
            for (int j = 0; j < 5; j++)
                #pragma unroll
                for (int i = 0; i < 5; i++)
                    o += A[j*5+i] * vs[j*WC + i];
            Ob[(size_t)(ck*CCH + c)*HW] = o;
        }
        __syncthreads();
    }
}

// ---------------------------------------------------------------------------
extern "C" void kernel_launch(void* const* d_in, const int* in_sizes, int n_in,
                              void* d_out, int out_size)
{
    const float* x  = (const float*)d_in[0];
    const float* y  = (const float*)d_in[1];
    const float* wx = (const float*)d_in[2];
    const float* bx = (const float*)d_in[3];
    const float* wy = (const float*)d_in[4];
    const float* by = (const float*)d_in[5];
    const float* wo = (const float*)d_in[6];
    const float* bo = (const float*)d_in[7];
    float* out = (float*)d_out;

    void *pQ, *pV, *pO;
    cudaGetSymbolAddress(&pQ, g_Q);
    cudaGetSymbolAddress(&pV, g_V);
    cudaGetSymbolAddress(&pO, g_O);

    cudaFuncSetAttribute(qv_conv_kernel,  cudaFuncAttributeMaxDynamicSharedMemorySize, CONV_SMEM);
    cudaFuncSetAttribute(out_conv_kernel, cudaFuncAttributeMaxDynamicSharedMemorySize, CONV_SMEM);
    cudaFuncSetAttribute(attn_kernel,     cudaFuncAttributeMaxDynamicSharedMemorySize, ATTN_SMEM);

    // q = wy @ y + by ; v = wx @ x + bx  (one fused launch, gridDim.y selects)
    qv_conv_kernel<<<dim3(NCTA, 2), 256, CONV_SMEM>>>(
        x, y, wx, bx, wy, by, (float*)pQ, (float*)pV);

    // scores + softmax + aggregate
    attn_kernel<<<dim3(128/WT, 128/HT, 4), 512, ATTN_SMEM>>>(
        (const float*)pQ, (const float*)pV, (float*)pO);

    // out = wo @ O + bo + x
    out_conv_kernel<<<NCTA, 256, CONV_SMEM>>>((const float*)pO, wo, bo, x, out);
}